// round 6
// baseline (speedup 1.0000x reference)
#include <cuda_runtime.h>
#include <math.h>

// Inputs (metadata order): y[16M] f32, mu[16M] f32, std[16M] f32, idx[200*100] i32
// Output: 1 x f32 (KL scalar)

#define NUM_SAMPLES 200
#define KDOF 100

// Scratch (no device allocation allowed). Winner resets for next graph replay.
__device__ float        g_s1 = 0.0f;   // sum of (q - K)
__device__ float        g_s2 = 0.0f;   // sum of (q - K)^2
__device__ unsigned int g_count = 0;

// 100 blocks x 256 threads: ONE CTA wave on 148 SMs (vs 2 waves at grid=200).
// Warps 0-3 handle sample 2b, warps 4-7 handle sample 2b+1.
__global__ void __launch_bounds__(256) fused_chi2_kl_kernel(
    const float* __restrict__ y,
    const float* __restrict__ mu,
    const float* __restrict__ sd,
    const int*   __restrict__ idx,
    float*       __restrict__ out)
{
    const int t    = threadIdx.x;
    const int half = t >> 7;                   // 0 or 1: which sample in block
    const int lane = t & 127;                  // position within the sample
    const int s    = blockIdx.x * 2 + half;

    // ---- Phase 1: per-sample chi-square statistic ----
    float v = 0.0f;
    if (lane < KDOF) {
        const int i = idx[s * KDOF + lane];
        // three independent gathers -> MLP=3 per thread
        const float d = __fdividef(y[i] - mu[i], sd[i]);
        v = d * d;
    }

    #pragma unroll
    for (int o = 16; o > 0; o >>= 1)
        v += __shfl_down_sync(0xFFFFFFFFu, v, o);

    __shared__ float sm[8];                    // 4 warps per sample x 2 samples
    if ((t & 31) == 0) sm[t >> 5] = v;
    __syncthreads();

    // One leader thread per sample folds its 4 warp sums into global moments.
    if (lane != 0) return;

    const int b = half * 4;
    const float p = (sm[b] + sm[b + 1] + sm[b + 2] + sm[b + 3]) - (float)KDOF;

    atomicAdd(&g_s1, p);
    atomicAdd(&g_s2, p * p);
    __threadfence();                           // publish sums before ticket

    if (atomicAdd(&g_count, 1u) != NUM_SAMPLES - 1u) return;

    // ---- Phase 2 (single thread, last sample to finish): KL ----
    __threadfence();                           // acquire: see all atomic sums

    const float s1 = g_s1;
    const float s2 = g_s2;

    const float inv_n = 1.0f / (float)NUM_SAMPLES;
    const float dm    = s1 * inv_n;                          // emp_mu - K
    const float var   = (s2 - s1 * s1 * inv_n)
                        * (1.0f / (float)(NUM_SAMPLES - 1)); // unbiased var
    const float two_k = 2.0f * (float)KDOF;

    out[0] = 0.5f * __logf(two_k / var)
           + (var + dm * dm) / (2.0f * two_k)
           - 0.5f;

    // Reset scratch for next replay.
    g_s1 = 0.0f;
    g_s2 = 0.0f;
    g_count = 0;
}

extern "C" void kernel_launch(void* const* d_in, const int* in_sizes, int n_in,
                              void* d_out, int out_size)
{
    const float* y   = (const float*)d_in[0];
    const float* mu  = (const float*)d_in[1];
    const float* sd  = (const float*)d_in[2];
    const int*   idx = (const int*)d_in[3];
    float* out = (float*)d_out;

    fused_chi2_kl_kernel<<<NUM_SAMPLES / 2, 256>>>(y, mu, sd, idx, out);
}

// round 7
// speedup vs baseline: 1.0257x; 1.0257x over previous
#include <cuda_runtime.h>
#include <math.h>

// Inputs (metadata order): y[16M] f32, mu[16M] f32, std[16M] f32, idx[200*100] i32
// Output: 1 x f32 (KL scalar)

#define NUM_SAMPLES 200
#define KDOF 100

// Scratch (no device allocation allowed). Winner resets for next graph replay.
__device__ float        g_s1 = 0.0f;   // sum of (q - K)
__device__ float        g_s2 = 0.0f;   // sum of (q - K)^2
__device__ unsigned int g_count = 0;

// Release-ordered reduction (no return value -> RED at LTS).
__device__ __forceinline__ void red_release_f32(float* addr, float val) {
    asm volatile("red.release.gpu.global.add.f32 [%0], %1;"
                 :: "l"(addr), "f"(val) : "memory");
}
// Acq-rel ticket: release makes our REDs visible, acquire lets the winner
// see everyone else's.
__device__ __forceinline__ unsigned int ticket_acq_rel(unsigned int* addr) {
    unsigned int old;
    asm volatile("atom.acq_rel.gpu.global.add.u32 %0, [%1], 1;"
                 : "=r"(old) : "l"(addr) : "memory");
    return old;
}
__device__ __forceinline__ float ld_acquire_f32(const float* addr) {
    float v;
    asm volatile("ld.acquire.gpu.global.f32 %0, [%1];"
                 : "=f"(v) : "l"(addr) : "memory");
    return v;
}

// 200 blocks x 128 threads (R4 geometry — best measured wall).
// Block s computes q_s, folds shifted moments via release-REDs; the last
// block (acq_rel ticket) computes the KL scalar. No MEMBARs anywhere.
__global__ void __launch_bounds__(128) fused_chi2_kl_kernel(
    const float* __restrict__ y,
    const float* __restrict__ mu,
    const float* __restrict__ sd,
    const int*   __restrict__ idx,
    float*       __restrict__ out)
{
    const int s = blockIdx.x;
    const int t = threadIdx.x;

    // ---- Phase 1: per-sample chi-square statistic ----
    float v = 0.0f;
    if (t < KDOF) {
        const int i = idx[s * KDOF + t];
        // three independent gathers -> MLP=3 per thread
        const float d = __fdividef(y[i] - mu[i], sd[i]);
        v = d * d;
    }

    #pragma unroll
    for (int o = 16; o > 0; o >>= 1)
        v += __shfl_down_sync(0xFFFFFFFFu, v, o);

    __shared__ float sm[4];
    if ((t & 31) == 0) sm[t >> 5] = v;
    __syncthreads();

    if (t != 0) return;

    // Shifted statistic p = q - K kills cancellation in the var formula.
    const float p = (sm[0] + sm[1] + sm[2] + sm[3]) - (float)KDOF;

    red_release_f32(&g_s1, p);
    red_release_f32(&g_s2, p * p);

    if (ticket_acq_rel(&g_count) != NUM_SAMPLES - 1u) return;

    // ---- Phase 2 (single thread, last block to tick): KL ----
    const float s1 = ld_acquire_f32(&g_s1);
    const float s2 = ld_acquire_f32(&g_s2);

    const float inv_n = 1.0f / (float)NUM_SAMPLES;
    const float dm    = s1 * inv_n;                          // emp_mu - K
    const float var   = (s2 - s1 * s1 * inv_n)
                        * (1.0f / (float)(NUM_SAMPLES - 1)); // unbiased var
    const float two_k = 2.0f * (float)KDOF;

    out[0] = 0.5f * __logf(two_k / var)
           + (var + dm * dm) / (2.0f * two_k)
           - 0.5f;

    // Reset scratch for next replay (plain stores; next launch's acquires
    // are ordered by the graph-replay launch boundary).
    g_s1 = 0.0f;
    g_s2 = 0.0f;
    g_count = 0;
}

extern "C" void kernel_launch(void* const* d_in, const int* in_sizes, int n_in,
                              void* d_out, int out_size)
{
    const float* y   = (const float*)d_in[0];
    const float* mu  = (const float*)d_in[1];
    const float* sd  = (const float*)d_in[2];
    const int*   idx = (const int*)d_in[3];
    float* out = (float*)d_out;

    fused_chi2_kl_kernel<<<NUM_SAMPLES, 128>>>(y, mu, sd, idx, out);
}